// round 1
// baseline (speedup 1.0000x reference)
#include <cuda_runtime.h>
#include <math_constants.h>

// ---------------------------------------------------------------------------
// ReverseLossLayer: loss = 0.5 * sum_m  min_n || src[n] - tar[m] ||^2
// src: [N,3] fp32, tar: [M,3] fp32, out: [1] fp32.  N = M = 16384 expected.
// No argmin needed: loss depends only on the min squared distance per target.
// ---------------------------------------------------------------------------

#define MAX_M 16384
__device__ unsigned g_min_bits[MAX_M];   // per-target min d2, as ordered uint bits

#define THREADS 256
#define TPT 2                      // targets per thread
#define TGT_PER_BLK (THREADS*TPT)  // 512 targets per block
#define NSPLIT 8                   // source-dimension splits (parallelism)
#define CHUNK 512                  // sources staged in smem per iteration

__global__ void rl_init_kernel(int M) {
    int i = blockIdx.x * blockDim.x + threadIdx.x;
    if (i < M) g_min_bits[i] = 0x7F800000u;  // +inf
}

__global__ __launch_bounds__(THREADS)
void rl_nn_kernel(const float* __restrict__ src, const float* __restrict__ tar,
                  int N, int M) {
    __shared__ float4 sh[CHUNK];

    const int tbase = blockIdx.x * TGT_PER_BLK;
    const int t0 = tbase + threadIdx.x;
    const int t1 = t0 + THREADS;

    // Target coords in registers
    const float t0x = tar[3*t0+0], t0y = tar[3*t0+1], t0z = tar[3*t0+2];
    const float t1x = tar[3*t1+0], t1y = tar[3*t1+1], t1z = tar[3*t1+2];

    const int per_split = N / NSPLIT;
    const int sbase = blockIdx.y * per_split;

    float mn0 = CUDART_INF_F;
    float mn1 = CUDART_INF_F;

    for (int c = 0; c < per_split; c += CHUNK) {
        // Cooperative stage of CHUNK sources into smem (padded float4)
        #pragma unroll
        for (int j = threadIdx.x; j < CHUNK; j += THREADS) {
            const int s = sbase + c + j;
            sh[j] = make_float4(src[3*s+0], src[3*s+1], src[3*s+2], 0.0f);
        }
        __syncthreads();

        #pragma unroll 8
        for (int j = 0; j < CHUNK; j++) {
            const float4 s = sh[j];  // broadcast LDS.128, conflict-free

            float dx0 = s.x - t0x, dy0 = s.y - t0y, dz0 = s.z - t0z;
            float d0  = dx0 * dx0;
            d0 = fmaf(dy0, dy0, d0);
            d0 = fmaf(dz0, dz0, d0);
            mn0 = fminf(mn0, d0);

            float dx1 = s.x - t1x, dy1 = s.y - t1y, dz1 = s.z - t1z;
            float d1  = dx1 * dx1;
            d1 = fmaf(dy1, dy1, d1);
            d1 = fmaf(dz1, dz1, d1);
            mn1 = fminf(mn1, d1);
        }
        __syncthreads();
    }

    // d2 >= 0, so uint bit-pattern compare == float compare
    atomicMin(&g_min_bits[t0], __float_as_uint(mn0));
    atomicMin(&g_min_bits[t1], __float_as_uint(mn1));
}

__global__ void rl_reduce_kernel(float* __restrict__ out, int M) {
    __shared__ float warpsum[32];
    float s = 0.0f;
    for (int i = threadIdx.x; i < M; i += blockDim.x)
        s += __uint_as_float(g_min_bits[i]);

    #pragma unroll
    for (int o = 16; o > 0; o >>= 1)
        s += __shfl_xor_sync(0xFFFFFFFFu, s, o);
    if ((threadIdx.x & 31) == 0) warpsum[threadIdx.x >> 5] = s;
    __syncthreads();

    if (threadIdx.x < 32) {
        const int nwarps = blockDim.x >> 5;
        s = (threadIdx.x < nwarps) ? warpsum[threadIdx.x] : 0.0f;
        #pragma unroll
        for (int o = 16; o > 0; o >>= 1)
            s += __shfl_xor_sync(0xFFFFFFFFu, s, o);
        if (threadIdx.x == 0) out[0] = 0.5f * s;
    }
}

extern "C" void kernel_launch(void* const* d_in, const int* in_sizes, int n_in,
                              void* d_out, int out_size) {
    const float* src = (const float*)d_in[0];   // [N,3]
    const float* tar = (const float*)d_in[1];   // [M,3]
    float* out = (float*)d_out;

    const int N = in_sizes[0] / 3;
    const int M = in_sizes[1] / 3;

    rl_init_kernel<<<(M + 255) / 256, 256>>>(M);

    dim3 grid(M / TGT_PER_BLK, NSPLIT);
    rl_nn_kernel<<<grid, THREADS>>>(src, tar, N, M);

    rl_reduce_kernel<<<1, 256>>>(out, M);
}

// round 2
// speedup vs baseline: 1.4907x; 1.4907x over previous
#include <cuda_runtime.h>
#include <math_constants.h>

// ---------------------------------------------------------------------------
// ReverseLossLayer: loss = 0.5 * sum_m  min_n || src[n] - tar[m] ||^2
// Expanded form: min_n (||s||^2 - 2 s.t)  + ||t||^2  (monotone-equivalent).
// Packed fma.rn.f32x2 processes 2 sources per instruction (sm_100+ only).
// ---------------------------------------------------------------------------

#define MAX_M 16384
__device__ unsigned g_min_bits[MAX_M];   // per-target min d2, ordered uint bits

#define THREADS 256
#define T 8                         // targets per thread
#define TGT_PER_BLK (THREADS * T)   // 2048
#define CHUNK 448                   // sources per split (one smem stage)
#define NSPLIT 37                   // 37*448 = 16576 >= 16384; grid = 8*37 = 296 = 2*148 SMs

typedef unsigned long long u64;

__device__ __forceinline__ u64 pack2(float a, float b) {
    u64 r;
    asm("mov.b64 %0, {%1, %2};" : "=l"(r) : "f"(a), "f"(b));
    return r;
}

// (lo,hi) = w01 + x01*nx + y01*ny + z01*nz   — lanewise over 2 packed sources
__device__ __forceinline__ void dot3x2(float& lo, float& hi,
                                       u64 x01, u64 y01, u64 z01, u64 w01,
                                       u64 nx, u64 ny, u64 nz) {
    asm("{\n\t"
        ".reg .b64 t;\n\t"
        "fma.rn.f32x2 t, %2, %5, %8;\n\t"
        "fma.rn.f32x2 t, %3, %6, t;\n\t"
        "fma.rn.f32x2 t, %4, %7, t;\n\t"
        "mov.b64 {%0, %1}, t;\n\t"
        "}"
        : "=f"(lo), "=f"(hi)
        : "l"(x01), "l"(y01), "l"(z01), "l"(nx), "l"(ny), "l"(nz), "l"(w01));
}

__global__ void rl_init_kernel(int M) {
    int i = blockIdx.x * blockDim.x + threadIdx.x;
    if (i < M) g_min_bits[i] = 0x7F800000u;  // +inf
}

__global__ __launch_bounds__(THREADS)
void rl_nn_kernel(const float* __restrict__ src, const float* __restrict__ tar,
                  int N) {
    __shared__ ulonglong2 sh_xy[CHUNK / 2];   // (x0,x1),(y0,y1) per source pair
    __shared__ ulonglong2 sh_zw[CHUNK / 2];   // (z0,z1),(|s0|^2,|s1|^2)

    const int tid = threadIdx.x;

    // ---- Stage CHUNK sources, pair-interleaved, with |s|^2 precomputed ----
    const int sbase = blockIdx.y * CHUNK;
    for (int j = tid; j < CHUNK / 2; j += THREADS) {
        const int s0 = sbase + 2 * j, s1 = s0 + 1;
        float x0 = 0.f, y0 = 0.f, z0 = 0.f, w0 = CUDART_INF_F;
        float x1 = 0.f, y1 = 0.f, z1 = 0.f, w1 = CUDART_INF_F;
        if (s0 < N) {
            x0 = src[3 * s0]; y0 = src[3 * s0 + 1]; z0 = src[3 * s0 + 2];
            w0 = fmaf(z0, z0, fmaf(y0, y0, x0 * x0));
        }
        if (s1 < N) {
            x1 = src[3 * s1]; y1 = src[3 * s1 + 1]; z1 = src[3 * s1 + 2];
            w1 = fmaf(z1, z1, fmaf(y1, y1, x1 * x1));
        }
        sh_xy[j] = make_ulonglong2(pack2(x0, x1), pack2(y0, y1));
        sh_zw[j] = make_ulonglong2(pack2(z0, z1), pack2(w0, w1));
    }

    // ---- Target coords: (-2t) packed into both f32x2 lanes, plus |t|^2 ----
    u64 nx[T], ny[T], nz[T];
    float tt[T], mlo[T], mhi[T];
    const int tbase = blockIdx.x * TGT_PER_BLK + tid;
    #pragma unroll
    for (int i = 0; i < T; i++) {
        const int t = tbase + i * THREADS;
        const float tx = tar[3 * t], ty = tar[3 * t + 1], tz = tar[3 * t + 2];
        nx[i] = pack2(-2.0f * tx, -2.0f * tx);
        ny[i] = pack2(-2.0f * ty, -2.0f * ty);
        nz[i] = pack2(-2.0f * tz, -2.0f * tz);
        tt[i] = fmaf(tz, tz, fmaf(ty, ty, tx * tx));
        mlo[i] = CUDART_INF_F;
        mhi[i] = CUDART_INF_F;
    }
    __syncthreads();

    // ---- Main loop: 2 sources x 8 targets per iteration ----
    for (int j = 0; j < CHUNK / 2; j++) {
        const ulonglong2 xy = sh_xy[j];   // LDS.128 broadcast
        const ulonglong2 zw = sh_zw[j];
        #pragma unroll
        for (int i = 0; i < T; i++) {
            float lo, hi;
            dot3x2(lo, hi, xy.x, xy.y, zw.x, zw.y, nx[i], ny[i], nz[i]);
            mlo[i] = fminf(mlo[i], lo);
            mhi[i] = fminf(mhi[i], hi);
        }
    }

    // ---- Combine lanes, restore +|t|^2, clamp >= 0, ordered-uint atomicMin ----
    #pragma unroll
    for (int i = 0; i < T; i++) {
        const float v = fmaxf(fminf(mlo[i], mhi[i]) + tt[i], 0.0f);
        atomicMin(&g_min_bits[tbase + i * THREADS], __float_as_uint(v));
    }
}

__global__ void rl_reduce_kernel(float* __restrict__ out, int M) {
    __shared__ float warpsum[32];
    float s = 0.0f;
    for (int i = threadIdx.x; i < M; i += blockDim.x)
        s += __uint_as_float(g_min_bits[i]);

    #pragma unroll
    for (int o = 16; o > 0; o >>= 1)
        s += __shfl_xor_sync(0xFFFFFFFFu, s, o);
    if ((threadIdx.x & 31) == 0) warpsum[threadIdx.x >> 5] = s;
    __syncthreads();

    if (threadIdx.x < 32) {
        const int nwarps = blockDim.x >> 5;
        s = (threadIdx.x < nwarps) ? warpsum[threadIdx.x] : 0.0f;
        #pragma unroll
        for (int o = 16; o > 0; o >>= 1)
            s += __shfl_xor_sync(0xFFFFFFFFu, s, o);
        if (threadIdx.x == 0) out[0] = 0.5f * s;
    }
}

extern "C" void kernel_launch(void* const* d_in, const int* in_sizes, int n_in,
                              void* d_out, int out_size) {
    const float* src = (const float*)d_in[0];   // [N,3]
    const float* tar = (const float*)d_in[1];   // [M,3]
    float* out = (float*)d_out;

    const int N = in_sizes[0] / 3;
    const int M = in_sizes[1] / 3;

    rl_init_kernel<<<(M + 255) / 256, 256>>>(M);

    dim3 grid(M / TGT_PER_BLK, NSPLIT);
    rl_nn_kernel<<<grid, THREADS>>>(src, tar, N);

    rl_reduce_kernel<<<1, 256>>>(out, M);
}